// round 9
// baseline (speedup 1.0000x reference)
#include <cuda_runtime.h>
#include <cuda_fp16.h>
#include <math.h>
#include <stdint.h>

#define B_   16
#define E_   768
#define H_   12
#define HD_  64
#define N_   197
#define NP_  196
#define L_   12
#define FF_  3072
#define ROWS_ (B_*N_)          // 3152
#define SQRTE 27.712812921102035f
#define EE_   (E_*E_)
#define FFE_  (FF_*E_)

// packed fp16 weight layout: [QKV(3*NQ)] [O(NQ)] [UG interleaved(2*NUP)] [DOWN(NUP)]
#define NQ_   (L_*EE_)
#define NUP_  (L_*FFE_)
#define OFF_QKV  0
#define OFF_O    (3*NQ_)
#define OFF_UG   (4*NQ_)
#define OFF_DOWN (4*NQ_ + 2*NUP_)
#define WTOT_    (4*NQ_ + 3*NUP_)

// ---------------- scratch (device globals; no allocation allowed) ----------
__device__ float g_h[ROWS_*E_];
__device__ float g_t[ROWS_*E_];
__device__ float g_qkv[ROWS_*3*E_];
__device__ __half g_act[ROWS_*E_];        // current-layer activations (K<=768 inputs)
__device__ __half g_act2[ROWS_*FF_];      // gated MLP hidden (K=3072 input to DOWN)
__device__ __half g_w[WTOT_];

// ======================= mma.sync GEMM ======================================
// C[M,N] = A[M,K] * W[N,K]^T ; A,W fp16, fp32 accum. 8 warps, warp 64x32,
// CTA 128x128, BK=32, 4-stage cp.async pipeline, 2 CTAs/SM.
// mode 0: write fp32 C.  mode 1: fused SiLU gating (interleaved u/g cols) ->
//         fp16 out[M][N/2] (separate buffer!), using s_u/s_v.
#define BM 128
#define BN 128
#define BK 32
#define PADE 40
#define ARR_BYTES (128*PADE*2)        // 10240
#define STAGE_BYTES (2*ARR_BYTES)     // 20480
#define NSTAGE 4
#define GSMEM (NSTAGE*STAGE_BYTES)    // 81920

__device__ __forceinline__ uint32_t smem_u32(const void* p) {
    uint32_t a;
    asm("{ .reg .u64 t; cvta.to.shared.u64 t, %1; cvt.u32.u64 %0, t; }"
        : "=r"(a) : "l"(p));
    return a;
}
__device__ __forceinline__ void cp16(uint32_t dst, const void* src) {
    asm volatile("cp.async.cg.shared.global [%0], [%1], 16;"
                 :: "r"(dst), "l"(src) : "memory");
}
#define CP_COMMIT() asm volatile("cp.async.commit_group;" ::: "memory")
#define CP_WAIT2()  asm volatile("cp.async.wait_group 2;" ::: "memory")

#define LDSM4(r, addr) \
    asm volatile("ldmatrix.sync.aligned.m8n8.x4.shared.b16 {%0,%1,%2,%3}, [%4];" \
        : "=r"((r)[0]), "=r"((r)[1]), "=r"((r)[2]), "=r"((r)[3]) : "r"(addr))
#define MMA_F16(d, a, b0, b1) \
    asm volatile("mma.sync.aligned.m16n8k16.row.col.f32.f16.f16.f32 " \
        "{%0,%1,%2,%3}, {%4,%5,%6,%7}, {%8,%9}, {%0,%1,%2,%3};" \
        : "+f"((d)[0]), "+f"((d)[1]), "+f"((d)[2]), "+f"((d)[3]) \
        : "r"((a)[0]), "r"((a)[1]), "r"((a)[2]), "r"((a)[3]), \
          "r"(b0), "r"(b1))

__device__ __forceinline__ void load_stage(
        uint32_t sbase,
        const __half* __restrict__ A, const __half* __restrict__ W,
        int m0, int n0, int k0, int M, int K, int tid) {
    #pragma unroll
    for (int i = 0; i < 4; i++) {
        int idx = tid + i*256;                 // 1024 total
        int arr = idx >> 9;
        int rem = idx & 511;
        int row = rem >> 2;
        int seg = rem & 3;
        uint32_t dst = sbase + arr*ARR_BYTES + row*(PADE*2) + seg*16;
        const __half* src;
        if (arr == 0) { int r = m0 + row; if (r >= M) r = M - 1;
                        src = A + (size_t)r*K + k0 + seg*8; }
        else          { src = W + (size_t)(n0 + row)*K + k0 + seg*8; }
        cp16(dst, src);
    }
}

__global__ __launch_bounds__(256, 2)
void gemm_mma(const __half* __restrict__ A,
              const __half* __restrict__ W,
              float* __restrict__ C, int M, int N, int K,
              int mode,
              const float* __restrict__ su, const float* __restrict__ sv,
              __half* __restrict__ hout) {
    extern __shared__ char smem[];
    const uint32_t sb = smem_u32(smem);
    const int tid = threadIdx.x;
    const int lane = tid & 31, wid = tid >> 5;      // 8 warps
    const int wm = (wid & 1) * 64;
    const int wn = (wid >> 1) * 32;
    const int m0 = blockIdx.y * BM, n0 = blockIdx.x * BN;

    float acc[4][4][4] = {};

    const int ntiles = K / BK;
    load_stage(sb,                 A, W, m0, n0, 0,    M, K, tid);
    CP_COMMIT();
    load_stage(sb + STAGE_BYTES,   A, W, m0, n0, BK,   M, K, tid);
    CP_COMMIT();
    load_stage(sb + 2*STAGE_BYTES, A, W, m0, n0, 2*BK, M, K, tid);
    CP_COMMIT();

    const int arow = lane & 15, acolsel = (lane >> 4) * 8;

    for (int t = 0; t < ntiles; t++) {
        CP_WAIT2();
        __syncthreads();
        if (t + 3 < ntiles)
            load_stage(sb + ((t + 3) % NSTAGE) * STAGE_BYTES,
                       A, W, m0, n0, (t + 3) * BK, M, K, tid);
        CP_COMMIT();

        uint32_t sbase = sb + (t % NSTAGE) * STAGE_BYTES;
        const uint32_t sA = sbase;
        const uint32_t sW = sbase + ARR_BYTES;

        #pragma unroll
        for (int ks = 0; ks < 2; ks++) {
            const int kb = ks * 16;
            uint32_t ar[4][4], bw[2][4];
            #pragma unroll
            for (int mt = 0; mt < 4; mt++) {
                uint32_t off = (wm + mt*16 + arow)*(PADE*2) + (kb + acolsel)*2;
                LDSM4(ar[mt], sA + off);
            }
            #pragma unroll
            for (int nb = 0; nb < 2; nb++) {
                uint32_t off = (wn + nb*16 + arow)*(PADE*2) + (kb + acolsel)*2;
                LDSM4(bw[nb], sW + off);
            }
            #pragma unroll
            for (int mt = 0; mt < 4; mt++)
                #pragma unroll
                for (int nb = 0; nb < 2; nb++) {
                    MMA_F16(acc[mt][2*nb],   ar[mt], bw[nb][0], bw[nb][2]);
                    MMA_F16(acc[mt][2*nb+1], ar[mt], bw[nb][1], bw[nb][3]);
                }
        }
        __syncthreads();
    }

    if (mode == 0) {
        #pragma unroll
        for (int mt = 0; mt < 4; mt++) {
            int rbase = m0 + wm + mt*16 + (lane >> 2);
            #pragma unroll
            for (int half = 0; half < 2; half++) {
                int r = rbase + half*8;
                if (r < M) {
                    float* crow = C + (size_t)r*N + n0 + wn + (lane & 3)*2;
                    #pragma unroll
                    for (int nt = 0; nt < 4; nt++) {
                        float2 v = make_float2(acc[mt][nt][half*2],
                                               acc[mt][nt][half*2 + 1]);
                        *reinterpret_cast<float2*>(crow + nt*8) = v;
                    }
                }
            }
        }
    } else {
        // fused SiLU gating: col pair (2j, 2j+1) = (u_j, g_j); out[M][N/2]
        const int NO = N >> 1;
        #pragma unroll
        for (int mt = 0; mt < 4; mt++) {
            int rbase = m0 + wm + mt*16 + (lane >> 2);
            #pragma unroll
            for (int half = 0; half < 2; half++) {
                int r = rbase + half*8;
                if (r < M) {
                    #pragma unroll
                    for (int nt = 0; nt < 4; nt++) {
                        int cbase = n0 + wn + (lane & 3)*2 + nt*8;
                        int j = cbase >> 1;
                        float u = acc[mt][nt][half*2]     * su[j];
                        float g = acc[mt][nt][half*2 + 1] * sv[j] * SQRTE;
                        float val = u * g / (1.0f + expf(-g));
                        hout[(size_t)r*NO + j] = __float2half(val);
                    }
                }
            }
        }
    }
}

// ---------------- merged weight fp32 -> fp16 repack (single launch) --------
__global__ void cvt_all(const float4* __restrict__ Wq, const float4* __restrict__ Wk,
                        const float4* __restrict__ Wv, const float4* __restrict__ Wo,
                        const float4* __restrict__ Wup, const float4* __restrict__ Wgate,
                        const float4* __restrict__ Wdown, __half2* __restrict__ dst) {
    int i = blockIdx.x * blockDim.x + threadIdx.x;     // over WTOT_/4
    const int NQ4 = NQ_/4, NUP4 = NUP_/4, EE4 = EE_/4, FFE4 = FFE_/4;
    float4 x;
    size_t de;
    if (i < 3*NQ4) {
        int f = i / NQ4, rem = i - f*NQ4;
        int l = rem / EE4, j = rem - l*EE4;
        x = (f == 0 ? Wq : (f == 1 ? Wk : Wv))[rem];
        de = (size_t)l*3*EE_ + (size_t)f*EE_ + (size_t)j*4;
    } else if (i < 4*NQ4) {
        int rem = i - 3*NQ4;
        x = Wo[rem];
        de = (size_t)OFF_O + (size_t)rem*4;
    } else if (i < 4*NQ4 + NUP4) {
        int rem = i - 4*NQ4;
        int l = rem / FFE4, j = rem - l*FFE4;
        int r = (j*4) / E_, c = (j*4) % E_;
        x = Wup[rem];
        de = (size_t)OFF_UG + (size_t)l*2*FFE_ + (size_t)(2*r)*E_ + c;
    } else if (i < 4*NQ4 + 2*NUP4) {
        int rem = i - 4*NQ4 - NUP4;
        int l = rem / FFE4, j = rem - l*FFE4;
        int r = (j*4) / E_, c = (j*4) % E_;
        x = Wgate[rem];
        de = (size_t)OFF_UG + (size_t)l*2*FFE_ + (size_t)(2*r + 1)*E_ + c;
    } else if (i < 4*NQ4 + 3*NUP4) {
        int rem = i - 4*NQ4 - 2*NUP4;
        x = Wdown[rem];
        de = (size_t)OFF_DOWN + (size_t)rem*4;
    } else return;
    size_t d2 = de >> 1;
    dst[d2]     = __half2(__float2half(x.x), __float2half(x.y));
    dst[d2 + 1] = __half2(__float2half(x.z), __float2half(x.w));
}

// ---------------- patch embed (writes fp32 h + fp16 act) --------------------
__global__ void patch_embed(const float* __restrict__ x,
                            const float* __restrict__ pw,
                            const float* __restrict__ pb,
                            const float* __restrict__ pos,
                            float* __restrict__ h,
                            __half* __restrict__ ah) {
    int bp = blockIdx.x;
    int b = bp / NP_, pidx = bp % NP_;
    int gi = pidx / 14, gj = pidx % 14;
    __shared__ float patch[768];
    for (int i = threadIdx.x; i < 768; i += blockDim.x) {
        int c  = i >> 8;
        int r  = i & 255;
        int ii = r >> 4, jj = r & 15;
        patch[i] = x[((b*3 + c)*224 + gi*16 + ii)*224 + gj*16 + jj];
    }
    __syncthreads();
    for (int e = threadIdx.x; e < E_; e += blockDim.x) {
        const float* w = pw + e*768;
        float acc = 0.f;
        #pragma unroll 8
        for (int i = 0; i < 768; i++) acc = fmaf(patch[i], w[i], acc);
        float val = acc + pb[e] + pos[(1 + pidx)*E_ + e];
        size_t oi = (size_t)(b*N_ + 1 + pidx)*E_ + e;
        h[oi] = val;
        ah[oi] = __float2half(val);
    }
}

__global__ void cls_pos(const float* __restrict__ cls,
                        const float* __restrict__ pos,
                        float* __restrict__ h,
                        __half* __restrict__ ah) {
    int b = blockIdx.x;
    for (int e = threadIdx.x; e < E_; e += blockDim.x) {
        float val = cls[e] + pos[e];
        size_t oi = (size_t)(b*N_)*E_ + e;
        h[oi] = val;
        ah[oi] = __float2half(val);
    }
}

// ---------------- fused attention: one block per (b,h), 2 blocks/SM ---------
#define AT_PAD 65
#define ASMEM_FLOATS (2*197*AT_PAD + 197 + 64 + 64 + 4*64 + 8 + 4)
#define ASMEM_BYTES  (ASMEM_FLOATS*4)

__global__ __launch_bounds__(256, 2)
void attn_fused(const float* __restrict__ qkv,
                const float* __restrict__ s_qk,
                __half* __restrict__ ah) {
    extern __shared__ float sm[];
    float* Ks = sm;
    float* Vs = Ks + 197*AT_PAD;
    float* lg = Vs + 197*AT_PAD;
    float* qs = lg + 197;
    float* ss = qs + 64;
    float* acc4 = ss + 64;
    float* red = acc4 + 256;
    float* invp = red + 8;

    int bh = blockIdx.x;
    int h = bh % H_, b = bh / H_;
    int tid = threadIdx.x, wid = tid >> 5, lane = tid & 31;
    const float* qb = qkv + (size_t)(b*N_)*(3*E_) + h*HD_;

    if (tid < 64) ss[tid] = s_qk[h*HD_ + tid] * SQRTE;
    for (int i = tid; i < 197*64; i += 256) {
        int m = i >> 6, d = i & 63;
        Ks[m*AT_PAD + d] = qb[(size_t)m*(3*E_) + E_ + d];
        Vs[m*AT_PAD + d] = qb[(size_t)m*(3*E_) + 2*E_ + d];
    }
    __syncthreads();
    for (int m = wid; m < N_; m += 8) {
        float v0 = Ks[m*AT_PAD + lane], v1 = Ks[m*AT_PAD + 32 + lane];
        float sq = v0*v0 + v1*v1;
        #pragma unroll
        for (int o = 16; o > 0; o >>= 1) sq += __shfl_xor_sync(~0u, sq, o);
        float inv = 1.f / fmaxf(sqrtf(sq), 1e-6f);
        Ks[m*AT_PAD + lane]      = v0 * inv * ss[lane];
        Ks[m*AT_PAD + 32 + lane] = v1 * inv * ss[lane + 32];
    }
    __syncthreads();

    for (int qn = 0; qn < N_; qn++) {
        if (wid == 0) {
            float v0 = qb[(size_t)qn*(3*E_) + lane];
            float v1 = qb[(size_t)qn*(3*E_) + 32 + lane];
            float sq = v0*v0 + v1*v1;
            #pragma unroll
            for (int o = 16; o > 0; o >>= 1) sq += __shfl_xor_sync(~0u, sq, o);
            float inv = 1.f / fmaxf(sqrtf(sq), 1e-6f);
            qs[lane]      = v0 * inv * ss[lane];
            qs[lane + 32] = v1 * inv * ss[lane + 32];
        }
        __syncthreads();
        float p = 0.f;
        if (tid < N_) {
            const float* kr = Ks + tid*AT_PAD;
            float sacc = 0.f;
            #pragma unroll
            for (int d = 0; d < 64; d++) sacc = fmaf(qs[d], kr[d], sacc);
            p = expf(sacc * 8.0f - 8.0f);
            lg[tid] = p;
        }
        float ws = p;
        #pragma unroll
        for (int o = 16; o > 0; o >>= 1) ws += __shfl_xor_sync(~0u, ws, o);
        if (lane == 0) red[wid] = ws;
        __syncthreads();
        if (tid == 0) {
            float s = 0.f;
            #pragma unroll
            for (int i = 0; i < 8; i++) s += red[i];
            invp[0] = 1.f / s;
        }
        int d = tid & 63, c = tid >> 6;
        float acc = 0.f;
        for (int m = c; m < N_; m += 4)
            acc = fmaf(lg[m], Vs[m*AT_PAD + d], acc);
        acc4[c*64 + d] = acc;
        __syncthreads();
        if (tid < 64) {
            float o2 = (acc4[tid] + acc4[64 + tid] + acc4[128 + tid] +
                        acc4[192 + tid]) * invp[0];
            size_t oi = ((size_t)(b*N_) + qn)*E_ + h*HD_ + tid;
            ah[oi] = __float2half(o2);
        }
        __syncthreads();
    }
}

// ---------------- residual + double cosine-norm (+ fp16 out) ----------------
__global__ __launch_bounds__(256)
void res_cn(float* __restrict__ h, const float* __restrict__ d,
            const float* __restrict__ alpha,
            __half* __restrict__ ah) {
    int row = blockIdx.x;
    int tid = threadIdx.x;
    const float* dr = d + (size_t)row*E_;
    float* hr = h + (size_t)row*E_;
    __shared__ float red[256];
    float dv[3], hv[3];
    float ss = 0.f;
    #pragma unroll
    for (int t = 0; t < 3; t++) {
        int e = tid + t*256;
        dv[t] = dr[e]; hv[t] = hr[e];
        ss += dv[t]*dv[t];
    }
    red[tid] = ss; __syncthreads();
    for (int s = 128; s > 0; s >>= 1) {
        if (tid < s) red[tid] += red[tid + s];
        __syncthreads();
    }
    float inv1 = 1.0f / fmaxf(sqrtf(red[0]), 1e-6f);
    __syncthreads();
    float y[3]; float ss2 = 0.f;
    #pragma unroll
    for (int t = 0; t < 3; t++) {
        int e = tid + t*256;
        float a = alpha[e] * (0.05f * SQRTE);
        y[t] = hv[t] + a*(dv[t]*inv1 - hv[t]);
        ss2 += y[t]*y[t];
    }
    red[tid] = ss2; __syncthreads();
    for (int s = 128; s > 0; s >>= 1) {
        if (tid < s) red[tid] += red[tid + s];
        __syncthreads();
    }
    float inv2 = 1.0f / fmaxf(sqrtf(red[0]), 1e-6f);
    #pragma unroll
    for (int t = 0; t < 3; t++) {
        int e = tid + t*256;
        float val = y[t]*inv2;
        hr[e] = val;
        ah[(size_t)row*E_ + e] = __float2half(val);
    }
}

// ---------------- LayerNorm tap -> output (drop CLS token) ------------------
__global__ __launch_bounds__(256)
void ln_out(const float* __restrict__ h, const float* __restrict__ w,
            const float* __restrict__ b, float* __restrict__ o) {
    int br = blockIdx.x;
    int bb = br / NP_, n = br % NP_ + 1;
    const float* hr = h + (size_t)(bb*N_ + n)*E_;
    float* orow = o + (size_t)br*E_;
    __shared__ float red[256];
    int tid = threadIdx.x;
    float vv[3];
    float s = 0.f;
    #pragma unroll
    for (int t = 0; t < 3; t++) { vv[t] = hr[tid + t*256]; s += vv[t]; }
    red[tid] = s; __syncthreads();
    for (int st = 128; st > 0; st >>= 1) {
        if (tid < st) red[tid] += red[tid + st];
        __syncthreads();
    }
    float mean = red[0] * (1.0f/E_);
    __syncthreads();
    float s2 = 0.f;
    #pragma unroll
    for (int t = 0; t < 3; t++) { float dd = vv[t] - mean; s2 += dd*dd; }
    red[tid] = s2; __syncthreads();
    for (int st = 128; st > 0; st >>= 1) {
        if (tid < st) red[tid] += red[tid + st];
        __syncthreads();
    }
    float inv = rsqrtf(red[0]*(1.0f/E_) + 1e-6f);
    #pragma unroll
    for (int t = 0; t < 3; t++) {
        int e = tid + t*256;
        orow[e] = (vv[t] - mean)*inv*w[e] + b[e];
    }
}

// ======================= driver ==============================================
extern "C" void kernel_launch(void* const* d_in, const int* in_sizes, int n_in,
                              void* d_out, int out_size) {
    (void)in_sizes; (void)n_in; (void)out_size;
    const float* x       = (const float*)d_in[0];
    const float* patch_w = (const float*)d_in[1];
    const float* patch_b = (const float*)d_in[2];
    const float* cls     = (const float*)d_in[3];
    const float* pos     = (const float*)d_in[4];
    const float* Wq      = (const float*)d_in[5];
    const float* Wk      = (const float*)d_in[6];
    const float* Wv      = (const float*)d_in[7];
    const float* Wo      = (const float*)d_in[8];
    const float* s_qk    = (const float*)d_in[9];
    const float* Wup     = (const float*)d_in[10];
    const float* Wgate   = (const float*)d_in[11];
    const float* Wdown   = (const float*)d_in[12];
    const float* s_u     = (const float*)d_in[13];
    const float* s_v     = (const float*)d_in[14];
    const float* aA      = (const float*)d_in[15];
    const float* aM      = (const float*)d_in[16];
    const float* fcw     = (const float*)d_in[17];
    const float* fcb     = (const float*)d_in[18];
    float* out = (float*)d_out;

    float *h, *t, *qkv;
    __half *ah, *a2, *wh;
    cudaGetSymbolAddress((void**)&h,   g_h);
    cudaGetSymbolAddress((void**)&t,   g_t);
    cudaGetSymbolAddress((void**)&qkv, g_qkv);
    cudaGetSymbolAddress((void**)&ah,  g_act);
    cudaGetSymbolAddress((void**)&a2,  g_act2);
    cudaGetSymbolAddress((void**)&wh,  g_w);

    cudaFuncSetAttribute(gemm_mma, cudaFuncAttributeMaxDynamicSharedMemorySize, GSMEM);
    cudaFuncSetAttribute(attn_fused, cudaFuncAttributeMaxDynamicSharedMemorySize, ASMEM_BYTES);

    // one merged weight conversion launch (keeps ncu -s 5 on hot kernels)
    cvt_all<<<(WTOT_/4 + 255)/256, 256>>>(
        (const float4*)Wq, (const float4*)Wk, (const float4*)Wv,
        (const float4*)Wo, (const float4*)Wup, (const float4*)Wgate,
        (const float4*)Wdown, (__half2*)wh);

    cls_pos<<<B_, 256>>>(cls, pos, h, ah);
    patch_embed<<<B_*NP_, 256>>>(x, patch_w, patch_b, pos, h, ah);

    dim3 gQKV(3*E_/BN, (ROWS_ + BM - 1)/BM);  // (18, 25)
    dim3 gE(E_/BN, (ROWS_ + BM - 1)/BM);      // (6, 25)
    dim3 gUG(2*FF_/BN, (ROWS_ + BM - 1)/BM);  // (48, 25)

    for (int l = 0; l < L_; l++) {
        const size_t oqkv = (size_t)l*3*EE_;
        const size_t oo   = (size_t)l*EE_;
        const size_t oug  = (size_t)l*2*FFE_;
        const size_t od   = (size_t)l*FFE_;
        gemm_mma<<<gQKV, 256, GSMEM>>>(ah, wh+OFF_QKV+oqkv, qkv, ROWS_, 3*E_, E_,
                                       0, nullptr, nullptr, nullptr);
        attn_fused<<<B_*H_, 256, ASMEM_BYTES>>>(qkv, s_qk + (size_t)l*H_*HD_, ah);
        gemm_mma<<<gE, 256, GSMEM>>>(ah, wh+OFF_O+oo, t, ROWS_, E_, E_,
                                     0, nullptr, nullptr, nullptr);
        res_cn<<<ROWS_, 256>>>(h, t, aA + (size_t)l*E_, ah);
        gemm_mma<<<gUG, 256, GSMEM>>>(ah, wh+OFF_UG+oug, nullptr, ROWS_, 2*FF_, E_,
                                      1, s_u + (size_t)l*FF_, s_v + (size_t)l*FF_, a2);
        gemm_mma<<<gE, 256, GSMEM>>>(a2, wh+OFF_DOWN+od, t, ROWS_, E_, FF_,
                                     0, nullptr, nullptr, nullptr);
        res_cn<<<ROWS_, 256>>>(h, t, aM + (size_t)l*E_, ah);
        if (l == L_ - 2)
            ln_out<<<B_*NP_, 256>>>(h, fcw, fcb, out);
    }
    ln_out<<<B_*NP_, 256>>>(h, fcw, fcb, out + (size_t)B_*NP_*E_);
}